// round 11
// baseline (speedup 1.0000x reference)
#include <cuda_runtime.h>
#include <cuda_bf16.h>
#include <math.h>

// ---------------------------------------------------------------------------
// EnhancedHybridModel: conv stack -> FC -> 4-qubit sim -> head.  B = 1024.
// All FFMA-bound kernels use packed fp32x2 FMA (fma.rn.f32x2).
// ---------------------------------------------------------------------------

#define B 1024
#define INVS 0.99999500003749968f   // 1/sqrt(1+1e-5)

typedef unsigned long long u64;

__device__ __forceinline__ u64 pk2(float lo, float hi) {
    u64 r; asm("mov.b64 %0, {%1,%2};" : "=l"(r) : "f"(lo), "f"(hi)); return r;
}
__device__ __forceinline__ float2 upk2(u64 v) {
    float2 f; asm("mov.b64 {%0,%1}, %2;" : "=f"(f.x), "=f"(f.y) : "l"(v)); return f;
}
__device__ __forceinline__ u64 fma2(u64 a, u64 b, u64 c) {
    u64 d; asm("fma.rn.f32x2 %0, %1, %2, %3;" : "=l"(d) : "l"(a), "l"(b), "l"(c)); return d;
}

__device__ float g_act1[B * 32 * 16 * 16];   // after conv1+pool
__device__ float g_act2[B * 64 * 8 * 8];     // after conv2+pool
__device__ float g_act3[B * 2048];           // after conv3+avgpool
__device__ float g_fc1p[4 * B * 512];        // fc1 split-K partials
__device__ float g_h512[B * 512];            // after FC1+ReLU
__device__ float2 g_Utot[16 * 16];           // total quantum unitary

// ---------------------------------------------------------------------------
// Kernel 1: conv1 (3->32) + BN + ReLU + maxpool.  One block per image.
// f32x2 paired over the two horizontal pooled positions; weights stored
// pre-duplicated (w,w) in smem; patch pairs hoisted to registers.
// ---------------------------------------------------------------------------
__global__ __launch_bounds__(256) void conv1_k(
    const float* __restrict__ x, const float* __restrict__ w,
    const float* __restrict__ bias, const float* __restrict__ gam,
    const float* __restrict__ bet)
{
    __shared__ float sin_[3 * 34 * 34];
    __shared__ u64  sw2[32 * 28];      // [oc][27->28] duplicated weights
    __shared__ float sa[32], sd[32];

    const int img = blockIdx.x;
    const int tid = threadIdx.x;

    for (int i = tid; i < 3 * 34 * 34; i += 256) sin_[i] = 0.f;
    for (int i = tid; i < 32 * 27; i += 256) {
        int oc = i / 27, kk = i - oc * 27;
        float v = w[i];
        sw2[oc * 28 + kk] = pk2(v, v);
    }
    if (tid < 32) {
        float a = gam[tid] * INVS;
        sa[tid] = a;
        sd[tid] = a * bias[tid] + bet[tid];
    }
    __syncthreads();

    const float* xp = x + (size_t)img * 3 * 32 * 32;
    for (int i = tid; i < 3 * 32 * 32; i += 256) {
        int c = i >> 10, y = (i >> 5) & 31, xx = i & 31;
        sin_[c * (34 * 34) + (y + 1) * 34 + (xx + 1)] = xp[i];
    }
    __syncthreads();

    const int py = tid >> 4, px = tid & 15;

    // patch pairs: pp_[c][r][kx] = (patch[r][kx], patch[r][kx+1]),
    // r = 0..3 (rows 2*py..2*py+3), kx = 0..2.  36 u64 registers.
    u64 pp_[3][4][3];
#pragma unroll
    for (int c = 0; c < 3; c++)
#pragma unroll
        for (int r = 0; r < 4; r++) {
            const float* row = sin_ + c * (34 * 34) + (2 * py + r) * 34 + 2 * px;
            float v0 = row[0], v1 = row[1], v2 = row[2], v3 = row[3];
            pp_[c][r][0] = pk2(v0, v1);
            pp_[c][r][1] = pk2(v1, v2);
            pp_[c][r][2] = pk2(v2, v3);
        }

    float* op = g_act1 + (size_t)img * 32 * 256 + py * 16 + px;

    for (int oc = 0; oc < 32; oc++) {
        u64 accT = 0ull, accB = 0ull;   // (a0,a1) top row, (a2,a3) bottom row
        const u64* wk = sw2 + oc * 28;
#pragma unroll
        for (int c = 0; c < 3; c++)
#pragma unroll
            for (int ky = 0; ky < 3; ky++)
#pragma unroll
                for (int kx = 0; kx < 3; kx++) {
                    u64 wv = wk[c * 9 + ky * 3 + kx];
                    accT = fma2(pp_[c][ky][kx],     wv, accT);
                    accB = fma2(pp_[c][ky + 1][kx], wv, accB);
                }
        float2 t = upk2(accT), b = upk2(accB);
        float a = sa[oc], d = sd[oc];
        float v0 = fmaxf(fmaf(a, t.x, d), 0.f);
        float v1 = fmaxf(fmaf(a, t.y, d), 0.f);
        float v2 = fmaxf(fmaf(a, b.x, d), 0.f);
        float v3 = fmaxf(fmaf(a, b.y, d), 0.f);
        op[oc * 256] = fmaxf(fmaxf(v0, v1), fmaxf(v2, v3));
    }
}

// ---------------------------------------------------------------------------
// Kernel 2: conv2 (32->64) + BN + ReLU + maxpool.  f32x2 paired over ocs.
// Grid (B, 2): 32 ocs/block = 16 oc-pairs. smem 82432B (2 CTAs/SM).
// ---------------------------------------------------------------------------
__global__ __launch_bounds__(256) void conv2_k(
    const float* __restrict__ w, const float* __restrict__ bias,
    const float* __restrict__ gam, const float* __restrict__ bet)
{
    extern __shared__ float sm[];
    float*  sin_ = sm;                        // 10368 floats
    float2* swp  = (float2*)(sm + 10368);     // [ic*160 + pair*10 + kk]
    __shared__ float sa[32], sd[32];

    const int img = blockIdx.x;
    const int ocBase = blockIdx.y * 32;
    const int tid = threadIdx.x;

    for (int i = tid; i < 10368; i += 256) sin_[i] = 0.f;
    for (int i = tid; i < 16 * 32 * 9; i += 256) {
        int j = i / 288, rem = i - j * 288;
        int ic = rem / 9, kk = rem - ic * 9;
        float lo = w[(size_t)(ocBase + 2 * j) * 288 + ic * 9 + kk];
        float hi = w[(size_t)(ocBase + 2 * j + 1) * 288 + ic * 9 + kk];
        swp[ic * 160 + j * 10 + kk] = make_float2(lo, hi);
    }
    if (tid < 32) {
        int oc = ocBase + tid;
        float a = gam[oc] * INVS;
        sa[tid] = a;
        sd[tid] = a * bias[oc] + bet[oc];
    }
    __syncthreads();

    const float* ip = g_act1 + (size_t)img * 32 * 256;
    for (int i = tid; i < 32 * 256; i += 256) {
        int c = i >> 8, y = (i >> 4) & 15, xx = i & 15;
        sin_[c * 324 + (y + 1) * 18 + (xx + 1)] = ip[i];
    }
    __syncthreads();

    const int pos = tid & 63;
    const int py = pos >> 3, px = pos & 7;
    const int og = tid >> 6;          // 0..3, 4 oc-pairs each

    u64 acc[4][4];
#pragma unroll
    for (int j = 0; j < 4; j++)
#pragma unroll
        for (int p = 0; p < 4; p++) acc[j][p] = 0ull;

    for (int ic = 0; ic < 32; ic++) {
        u64 d[4][4];
        const float* sp = sin_ + ic * 324 + (2 * py) * 18 + 2 * px;
#pragma unroll
        for (int dy = 0; dy < 4; dy++) {
            float2 v0 = *(const float2*)(sp + dy * 18);
            float2 v1 = *(const float2*)(sp + dy * 18 + 2);
            d[dy][0] = pk2(v0.x, v0.x);
            d[dy][1] = pk2(v0.y, v0.y);
            d[dy][2] = pk2(v1.x, v1.x);
            d[dy][3] = pk2(v1.y, v1.y);
        }

#pragma unroll
        for (int j = 0; j < 4; j++) {
            const ulonglong2* wq =
                (const ulonglong2*)(swp + ic * 160 + (og * 4 + j) * 10);
            ulonglong2 q0 = wq[0], q1 = wq[1];
            ulonglong2 q2 = wq[2];
            ulonglong2 q3 = wq[3];
            ulonglong2 q4 = wq[4];
            u64 wk[9] = { q0.x, q0.y, q1.x, q1.y, q2.x, q2.y, q3.x, q3.y, q4.x };
#pragma unroll
            for (int kk = 0; kk < 9; kk++) {
                int ky = kk / 3, kx = kk - ky * 3;
                acc[j][0] = fma2(d[ky][kx],         wk[kk], acc[j][0]);
                acc[j][1] = fma2(d[ky][kx + 1],     wk[kk], acc[j][1]);
                acc[j][2] = fma2(d[ky + 1][kx],     wk[kk], acc[j][2]);
                acc[j][3] = fma2(d[ky + 1][kx + 1], wk[kk], acc[j][3]);
            }
        }
    }

    float* op = g_act2 + (size_t)img * 64 * 64 + pos;
#pragma unroll
    for (int j = 0; j < 4; j++) {
        float2 v0 = upk2(acc[j][0]), v1 = upk2(acc[j][1]);
        float2 v2 = upk2(acc[j][2]), v3 = upk2(acc[j][3]);
        int lo0 = og * 8 + 2 * j, lo1 = lo0 + 1;
        {
            float a = sa[lo0], dd = sd[lo0];
            float m = fmaxf(fmaxf(fmaxf(fmaf(a, v0.x, dd), 0.f),
                                  fmaxf(fmaf(a, v1.x, dd), 0.f)),
                            fmaxf(fmaxf(fmaf(a, v2.x, dd), 0.f),
                                  fmaxf(fmaf(a, v3.x, dd), 0.f)));
            op[(ocBase + lo0) * 64] = m;
        }
        {
            float a = sa[lo1], dd = sd[lo1];
            float m = fmaxf(fmaxf(fmaxf(fmaf(a, v0.y, dd), 0.f),
                                  fmaxf(fmaf(a, v1.y, dd), 0.f)),
                            fmaxf(fmaxf(fmaf(a, v2.y, dd), 0.f),
                                  fmaxf(fmaf(a, v3.y, dd), 0.f)));
            op[(ocBase + lo1) * 64] = m;
        }
    }
}

// ---------------------------------------------------------------------------
// Kernel 3: conv3 (64->128) + BN + ReLU + avgpool.  f32x2 paired over ocs.
// Grid (B, 4): 32 ocs/block = 16 pairs, 1 pair per thread-group.
// ---------------------------------------------------------------------------
__global__ __launch_bounds__(256) void conv3_k(
    const float* __restrict__ w, const float* __restrict__ bias,
    const float* __restrict__ gam, const float* __restrict__ bet)
{
    extern __shared__ float sm[];
    float*  sin_ = sm;                        // 6400 floats
    float2* swp  = (float2*)(sm + 6400);      // [ic*160 + pair*10 + kk]
    __shared__ float sa[32], sd[32];

    const int img = blockIdx.x;
    const int ocBase = blockIdx.y * 32;
    const int tid = threadIdx.x;

    for (int i = tid; i < 6400; i += 256) sin_[i] = 0.f;
    for (int i = tid; i < 16 * 64 * 9; i += 256) {
        int j = i / 576, rem = i - j * 576;
        int ic = rem / 9, kk = rem - ic * 9;
        float lo = w[(size_t)(ocBase + 2 * j) * 576 + ic * 9 + kk];
        float hi = w[(size_t)(ocBase + 2 * j + 1) * 576 + ic * 9 + kk];
        swp[ic * 160 + j * 10 + kk] = make_float2(lo, hi);
    }
    if (tid < 32) {
        int oc = ocBase + tid;
        float a = gam[oc] * INVS;
        sa[tid] = a;
        sd[tid] = a * bias[oc] + bet[oc];
    }
    __syncthreads();

    const float* ip = g_act2 + (size_t)img * 64 * 64;
    for (int i = tid; i < 64 * 64; i += 256) {
        int c = i >> 6, y = (i >> 3) & 7, xx = i & 7;
        sin_[c * 100 + (y + 1) * 10 + (xx + 1)] = ip[i];
    }
    __syncthreads();

    const int pos = tid & 15;
    const int py = pos >> 2, px = pos & 3;
    const int og = tid >> 4;          // 0..15, one oc-pair each

    u64 acc[4];
#pragma unroll
    for (int p = 0; p < 4; p++) acc[p] = 0ull;

    for (int ic = 0; ic < 64; ic++) {
        u64 d[4][4];
        const float* sp = sin_ + ic * 100 + (2 * py) * 10 + 2 * px;
#pragma unroll
        for (int dy = 0; dy < 4; dy++) {
            float2 v0 = *(const float2*)(sp + dy * 10);
            float2 v1 = *(const float2*)(sp + dy * 10 + 2);
            d[dy][0] = pk2(v0.x, v0.x);
            d[dy][1] = pk2(v0.y, v0.y);
            d[dy][2] = pk2(v1.x, v1.x);
            d[dy][3] = pk2(v1.y, v1.y);
        }

        const ulonglong2* wq = (const ulonglong2*)(swp + ic * 160 + og * 10);
        ulonglong2 q0 = wq[0], q1 = wq[1], q2 = wq[2], q3 = wq[3], q4 = wq[4];
        u64 wk[9] = { q0.x, q0.y, q1.x, q1.y, q2.x, q2.y, q3.x, q3.y, q4.x };
#pragma unroll
        for (int kk = 0; kk < 9; kk++) {
            int ky = kk / 3, kx = kk - ky * 3;
            acc[0] = fma2(d[ky][kx],         wk[kk], acc[0]);
            acc[1] = fma2(d[ky][kx + 1],     wk[kk], acc[1]);
            acc[2] = fma2(d[ky + 1][kx],     wk[kk], acc[2]);
            acc[3] = fma2(d[ky + 1][kx + 1], wk[kk], acc[3]);
        }
    }

    {
        float2 v0 = upk2(acc[0]), v1 = upk2(acc[1]);
        float2 v2 = upk2(acc[2]), v3 = upk2(acc[3]);
        int lo0 = 2 * og, lo1 = lo0 + 1;
        float a = sa[lo0], dd = sd[lo0];
        float s = fmaxf(fmaf(a, v0.x, dd), 0.f) + fmaxf(fmaf(a, v1.x, dd), 0.f)
                + fmaxf(fmaf(a, v2.x, dd), 0.f) + fmaxf(fmaf(a, v3.x, dd), 0.f);
        g_act3[(size_t)img * 2048 + (ocBase + lo0) * 16 + pos] = 0.25f * s;
        a = sa[lo1]; dd = sd[lo1];
        s = fmaxf(fmaf(a, v0.y, dd), 0.f) + fmaxf(fmaf(a, v1.y, dd), 0.f)
          + fmaxf(fmaf(a, v2.y, dd), 0.f) + fmaxf(fmaf(a, v3.y, dd), 0.f);
        g_act3[(size_t)img * 2048 + (ocBase + lo1) * 16 + pos] = 0.25f * s;
    }
}

// ---------------------------------------------------------------------------
// Kernel 4a: FC1 split-K partial.  grid (8, 16, 4): 512 CTAs.
// A-tile stored in smem PRE-DUPLICATED as (a,a) u64 pairs; B-tile's natural
// float4 layout provides packed (b0,b1),(b2,b3) operands.  8 fma2 per kk.
// ---------------------------------------------------------------------------
__global__ __launch_bounds__(256) void fc1_k(const float* __restrict__ W)
{
    __shared__ u64  As2[16 * 68];   // [kk][row] duplicated, 8704B
    __shared__ float Bs[16 * 68];   // [kk][col], 4352B

    const int obase = blockIdx.x * 64;
    const int nbase = blockIdx.y * 64;
    const int kz    = blockIdx.z;
    const int tid = threadIdx.x;
    const int ty = tid >> 4, tx = tid & 15;

    const int lr = tid >> 2;
    const int lc = (tid & 3) * 4;

    u64 acc2[4][2];                 // [row i][col-pair]: (j0,j1),(j2,j3)
#pragma unroll
    for (int i = 0; i < 4; i++) { acc2[i][0] = 0ull; acc2[i][1] = 0ull; }

    const int kbeg = kz * 512, kend = kbeg + 512;
    for (int k0 = kbeg; k0 < kend; k0 += 16) {
        float4 av = *(const float4*)(g_act3 + (size_t)(nbase + lr) * 2048 + k0 + lc);
        float4 bv = *(const float4*)(W + (size_t)(obase + lr) * 2048 + k0 + lc);
        As2[(lc + 0) * 68 + lr] = pk2(av.x, av.x);
        As2[(lc + 1) * 68 + lr] = pk2(av.y, av.y);
        As2[(lc + 2) * 68 + lr] = pk2(av.z, av.z);
        As2[(lc + 3) * 68 + lr] = pk2(av.w, av.w);
        Bs[(lc + 0) * 68 + lr] = bv.x;
        Bs[(lc + 1) * 68 + lr] = bv.y;
        Bs[(lc + 2) * 68 + lr] = bv.z;
        Bs[(lc + 3) * 68 + lr] = bv.w;
        __syncthreads();
#pragma unroll
        for (int kk = 0; kk < 16; kk++) {
            const ulonglong2* aq = (const ulonglong2*)&As2[kk * 68 + ty * 4];
            ulonglong2 a01 = aq[0];      // dup(a0), dup(a1)
            ulonglong2 a23 = aq[1];      // dup(a2), dup(a3)
            ulonglong2 bb = *(const ulonglong2*)&Bs[kk * 68 + tx * 4];
            // bb.x = (b0,b1), bb.y = (b2,b3)
            acc2[0][0] = fma2(a01.x, bb.x, acc2[0][0]);
            acc2[0][1] = fma2(a01.x, bb.y, acc2[0][1]);
            acc2[1][0] = fma2(a01.y, bb.x, acc2[1][0]);
            acc2[1][1] = fma2(a01.y, bb.y, acc2[1][1]);
            acc2[2][0] = fma2(a23.x, bb.x, acc2[2][0]);
            acc2[2][1] = fma2(a23.x, bb.y, acc2[2][1]);
            acc2[3][0] = fma2(a23.y, bb.x, acc2[3][0]);
            acc2[3][1] = fma2(a23.y, bb.y, acc2[3][1]);
        }
        __syncthreads();
    }

    float* pp = g_fc1p + (size_t)kz * B * 512;
#pragma unroll
    for (int i = 0; i < 4; i++) {
        int n = nbase + ty * 4 + i;
        ulonglong2 st;
        st.x = acc2[i][0];
        st.y = acc2[i][1];
        *(ulonglong2*)&pp[(size_t)n * 512 + obase + tx * 4] = st;
    }
}

// ---------------------------------------------------------------------------
// Kernel 4b: FC1 reduce.
// ---------------------------------------------------------------------------
__global__ __launch_bounds__(256) void fc1_red(const float* __restrict__ bias)
{
    const int idx = blockIdx.x * 256 + threadIdx.x;
    const int e0 = idx * 4;
    const int o = e0 & 511;

    float4 s0 = *(const float4*)(g_fc1p + e0);
    float4 s1 = *(const float4*)(g_fc1p + (size_t)B * 512 + e0);
    float4 s2 = *(const float4*)(g_fc1p + (size_t)2 * B * 512 + e0);
    float4 s3 = *(const float4*)(g_fc1p + (size_t)3 * B * 512 + e0);
    float4 bv = *(const float4*)(bias + o);

    float4 r;
    r.x = fmaxf(s0.x + s1.x + s2.x + s3.x + bv.x, 0.f);
    r.y = fmaxf(s0.y + s1.y + s2.y + s3.y + bv.y, 0.f);
    r.z = fmaxf(s0.z + s1.z + s2.z + s3.z + bv.z, 0.f);
    r.w = fmaxf(s0.w + s1.w + s2.w + s3.w + bv.w, 0.f);
    *(float4*)(g_h512 + e0) = r;
}

// ---------------------------------------------------------------------------
// Kernel 5: build total 16x16 complex unitary from q_weights.
// ---------------------------------------------------------------------------
__global__ void qprep_k(const float* __restrict__ qw)
{
    __shared__ float2 U1[256], U2[256];
    const int tid = threadIdx.x;
    const int i = tid >> 4, j = tid & 15;

    for (int l = 0; l < 2; l++) {
        float re = 1.f, im = 0.f;
#pragma unroll
        for (int q = 0; q < 4; q++) {
            float th = qw[l * 4 + q] * 0.5f;
            float c = cosf(th), s = sinf(th);
            int bi = (i >> (3 - q)) & 1, bj = (j >> (3 - q)) & 1;
            if (bi == bj) { re *= c; im *= c; }
            else { float nr = im * s, ni = -re * s; re = nr; im = ni; }
        }
        int bb = i;
        if ((bb >> 3) & 1) bb ^= 4;
        if ((bb >> 2) & 1) bb ^= 2;
        if ((bb >> 1) & 1) bb ^= 1;
        if (bb & 1)        bb ^= 8;
        float2 v = make_float2(re, im);
        if (l == 0) U1[bb * 16 + j] = v; else U2[bb * 16 + j] = v;
    }
    __syncthreads();

    float ar = 0.f, ai = 0.f;
#pragma unroll
    for (int k = 0; k < 16; k++) {
        float2 a = U2[i * 16 + k], b = U1[k * 16 + j];
        ar += a.x * b.x - a.y * b.y;
        ai += a.x * b.y + a.y * b.x;
    }
    g_Utot[tid] = make_float2(ar, ai);
}

// ---------------------------------------------------------------------------
// Kernel 6: fused tail per sample. grid B, 128 threads.
// ---------------------------------------------------------------------------
__global__ __launch_bounds__(128) void tail_k(
    const float* __restrict__ fr2w, const float* __restrict__ fr2b,
    const float* __restrict__ h1w,  const float* __restrict__ h1b,
    const float* __restrict__ bnhg, const float* __restrict__ bnhb,
    const float* __restrict__ h2w,  const float* __restrict__ h2b,
    float* __restrict__ out)
{
    __shared__ float sh[512];
    __shared__ float2 sU[256];
    __shared__ float logits[16];
    __shared__ float psi[16];
    __shared__ float probs[16];
    __shared__ float qv[4];
    __shared__ float t1[128];

    const int bimg = blockIdx.x;
    const int tid = threadIdx.x;

    const float* hp = g_h512 + (size_t)bimg * 512;
    for (int i = tid; i < 512; i += 128) sh[i] = hp[i];
    sU[tid] = g_Utot[tid];
    sU[tid + 128] = g_Utot[tid + 128];
    __syncthreads();

    {
        int o = tid >> 3, c = tid & 7;
        const float* wr = fr2w + (size_t)o * 512 + c * 64;
        const float* hr = sh + c * 64;
        float s = 0.f;
#pragma unroll 8
        for (int k = 0; k < 64; k++) s = fmaf(hr[k], wr[k], s);
        s += __shfl_xor_sync(0xffffffffu, s, 4, 8);
        s += __shfl_xor_sync(0xffffffffu, s, 2, 8);
        s += __shfl_xor_sync(0xffffffffu, s, 1, 8);
        if (c == 0) logits[o] = s + fr2b[o];
    }
    __syncthreads();

    if (tid < 16) {
        float v = logits[tid];
        float m = v;
#pragma unroll
        for (int off = 8; off > 0; off >>= 1)
            m = fmaxf(m, __shfl_xor_sync(0x0000ffffu, m, off, 16));
        float e = expf(v - m);
        float sum = e;
#pragma unroll
        for (int off = 8; off > 0; off >>= 1)
            sum += __shfl_xor_sync(0x0000ffffu, sum, off, 16);
        float f = e / sum;
        float s2 = f * f;
#pragma unroll
        for (int off = 8; off > 0; off >>= 1)
            s2 += __shfl_xor_sync(0x0000ffffu, s2, off, 16);
        psi[tid] = f / sqrtf(s2);
    }
    __syncthreads();

    if (tid < 16) {
        float yr = 0.f, yi = 0.f;
#pragma unroll
        for (int jj = 0; jj < 16; jj++) {
            float2 u = sU[tid * 16 + jj];
            float p = psi[jj];
            yr = fmaf(u.x, p, yr);
            yi = fmaf(u.y, p, yi);
        }
        probs[tid] = yr * yr + yi * yi;
    }
    __syncthreads();

    if (tid < 4) {
        float e = 0.f;
#pragma unroll
        for (int bb = 0; bb < 16; bb++) {
            float z = 1.f - 2.f * (float)((bb >> (3 - tid)) & 1);
            e = fmaf(probs[bb], z, e);
        }
        qv[tid] = e;
    }
    __syncthreads();

    {
        float v = h1b[tid];
#pragma unroll
        for (int k = 0; k < 4; k++) v = fmaf(h1w[tid * 4 + k], qv[k], v);
        v = fmaf(bnhg[tid] * INVS, v, bnhb[tid]);
        t1[tid] = fmaxf(v, 0.f);
    }
    __syncthreads();

    if (tid < 100) {
        const float* wr = h2w + (size_t)tid * 128;
        float s = h2b[tid];
#pragma unroll 8
        for (int jj = 0; jj < 128; jj++) s = fmaf(t1[jj], wr[jj], s);
        out[(size_t)bimg * 100 + tid] = s;
    }
}

// ---------------------------------------------------------------------------
// Launch
// ---------------------------------------------------------------------------
extern "C" void kernel_launch(void* const* d_in, const int* in_sizes, int n_in,
                              void* d_out, int out_size)
{
    const float* x       = (const float*)d_in[0];
    const float* conv1_w = (const float*)d_in[1];
    const float* conv1_b = (const float*)d_in[2];
    const float* bn1_g   = (const float*)d_in[3];
    const float* bn1_b   = (const float*)d_in[4];
    const float* conv2_w = (const float*)d_in[5];
    const float* conv2_b = (const float*)d_in[6];
    const float* bn2_g   = (const float*)d_in[7];
    const float* bn2_b   = (const float*)d_in[8];
    const float* conv3_w = (const float*)d_in[9];
    const float* conv3_b = (const float*)d_in[10];
    const float* bn3_g   = (const float*)d_in[11];
    const float* bn3_b   = (const float*)d_in[12];
    const float* fr1_w   = (const float*)d_in[13];
    const float* fr1_b   = (const float*)d_in[14];
    const float* fr2_w   = (const float*)d_in[15];
    const float* fr2_b   = (const float*)d_in[16];
    const float* q_w     = (const float*)d_in[17];
    const float* h1_w    = (const float*)d_in[18];
    const float* h1_b    = (const float*)d_in[19];
    const float* bnh_g   = (const float*)d_in[20];
    const float* bnh_b   = (const float*)d_in[21];
    const float* h2_w    = (const float*)d_in[22];
    const float* h2_b    = (const float*)d_in[23];
    float* out = (float*)d_out;

    cudaFuncSetAttribute(conv2_k, cudaFuncAttributeMaxDynamicSharedMemorySize, 82432);
    cudaFuncSetAttribute(conv3_k, cudaFuncAttributeMaxDynamicSharedMemorySize, 107520);

    conv1_k<<<B, 256>>>(x, conv1_w, conv1_b, bn1_g, bn1_b);
    conv2_k<<<dim3(B, 2), 256, 82432>>>(conv2_w, conv2_b, bn2_g, bn2_b);
    conv3_k<<<dim3(B, 4), 256, 107520>>>(conv3_w, conv3_b, bn3_g, bn3_b);
    fc1_k<<<dim3(8, 16, 4), 256>>>(fr1_w);
    fc1_red<<<512, 256>>>(fr1_b);
    qprep_k<<<1, 256>>>(q_w);
    tail_k<<<B, 128>>>(fr2_w, fr2_b, h1_w, h1_b, bnh_g, bnh_b, h2_w, h2_b, out);
}